// round 16
// baseline (speedup 1.0000x reference)
#include <cuda_runtime.h>
#include <cuda_fp16.h>
#include <math.h>
#include <stdint.h>

#define N_ENT  50000
#define N_PAD  50048           // 391 * 128
#define N_EDGE 500000
#define H      128

typedef unsigned long long ull;

// ================= scratch (static __device__, zero-init at load) =========
// g_deg and g_base are re-zeroed by k_gemm3 at the end of every call.
__device__ int      g_deg[N_ENT];
__device__ int      g_off[N_ENT];
__device__ int      g_base;
__device__ __align__(16) int      g_rank[N_EDGE];  // edge rank within dst segment
__device__ unsigned g_pk[N_EDGE];                  // packed src*512 + rel_id
__device__ __align__(16) __half g_a[3][N_PAD * H]; // neigh fp16 (pad rows stay 0)
__device__ __align__(16) __half g_wt[3][H * H];    // W^T fp16 (h-major rows)

// ================= helpers =================
__device__ __forceinline__ float fast_tanh(float x) {
    float e = __expf(2.f * x);
    return 1.f - __fdividef(2.f, e + 1.f);
}
__device__ __forceinline__ uint32_t smem_u32(const void* p) {
    uint32_t a;
    asm("{ .reg .u64 t; cvta.to.shared.u64 t, %1; cvt.u32.u64 %0, t; }" : "=r"(a) : "l"(p));
    return a;
}
// ---- packed f32x2 ops (sm_100+ PTX; FFMA2/FADD2 in SASS) ----
__device__ __forceinline__ void fma2(ull& acc, ull a, ull b) {
    asm("fma.rn.f32x2 %0, %1, %2, %0;" : "+l"(acc) : "l"(a), "l"(b));
}
__device__ __forceinline__ ull mul2(ull a, ull b) {
    ull d; asm("mul.rn.f32x2 %0, %1, %2;" : "=l"(d) : "l"(a), "l"(b)); return d;
}
__device__ __forceinline__ ull add2(ull a, ull b) {
    ull d; asm("add.rn.f32x2 %0, %1, %2;" : "=l"(d) : "l"(a), "l"(b)); return d;
}
__device__ __forceinline__ ull dup2(float x) {
    ull d; asm("mov.b64 %0, {%1, %1};" : "=l"(d) : "f"(x)); return d;
}
__device__ __forceinline__ float2 unp2(ull a) {
    float2 r; asm("mov.b64 {%0, %1}, %2;" : "=f"(r.x), "=f"(r.y) : "l"(a)); return r;
}
// dot of two 4-vectors held as (01,23) f32x2 pairs: MUL2 + FMA2 + FADD
__device__ __forceinline__ float dot4p(ull u01, ull u23, ull v01, ull v23) {
    ull t = mul2(u01, v01);
    asm("fma.rn.f32x2 %0, %1, %2, %0;" : "+l"(t) : "l"(u23), "l"(v23));
    float2 f = unp2(t);
    return f.x + f.y;
}
#define LDSM4(R0, R1, R2, R3, addr) \
    asm volatile("ldmatrix.sync.aligned.m8n8.x4.shared.b16 {%0,%1,%2,%3}, [%4];" \
        : "=r"(R0), "=r"(R1), "=r"(R2), "=r"(R3) : "r"(addr))
#define MMA16816(C, A0, A1, A2, A3, B0, B1) \
    asm volatile("mma.sync.aligned.m16n8k16.row.col.f32.f16.f16.f32 " \
        "{%0,%1,%2,%3}, {%4,%5,%6,%7}, {%8,%9}, {%0,%1,%2,%3};" \
        : "+f"((C)[0]), "+f"((C)[1]), "+f"((C)[2]), "+f"((C)[3]) \
        : "r"(A0), "r"(A1), "r"(A2), "r"(A3), "r"(B0), "r"(B1))
#define CP16(sm_addr, gptr) \
    asm volatile("cp.async.cg.shared.global [%0], [%1], 16;" :: "r"(sm_addr), "l"(gptr))
#define CP_COMMIT() asm volatile("cp.async.commit_group;")
#define CP_WAIT0()  asm volatile("cp.async.wait_group 0;")

// ================= K1: degree histogram, 4 edges/thread ==================
__global__ void k_hist(const int* __restrict__ dst) {
    int t = blockIdx.x * blockDim.x + threadIdx.x;
    if (t >= N_EDGE / 4) return;
    int4 d4 = ((const int4*)dst)[t];
    int4 r4;
    r4.x = atomicAdd(&g_deg[d4.x], 1);
    r4.y = atomicAdd(&g_deg[d4.y], 1);
    r4.z = atomicAdd(&g_deg[d4.z], 1);
    r4.w = atomicAdd(&g_deg[d4.w], 1);
    ((int4*)g_rank)[t] = r4;
}

// ================= K2: parallel CSR offsets + W^T fp16 prep ==============
__global__ void __launch_bounds__(256)
k_alloc(const float* __restrict__ we, const float* __restrict__ wn,
        const float* __restrict__ wc) {
    int t = threadIdx.x;
    int i = blockIdx.x * 256 + t;

    if (i < 3 * H * H) {
        int l = i >> 14, r = i & 16383;
        int k = r >> 7, h = r & 127;
        const float* W = (l == 0) ? we : (l == 1) ? wn : wc;
        g_wt[l][h * H + k] = __float2half(W[k * H + h]);
    }

    int d = (i < N_ENT) ? g_deg[i] : 0;
    int lane = t & 31, wid = t >> 5;
    int x = d;
    #pragma unroll
    for (int o = 1; o < 32; o <<= 1) {
        int y = __shfl_up_sync(0xffffffffu, x, o);
        if (lane >= o) x += y;
    }
    __shared__ int wsum[8];
    __shared__ int blockbase;
    if (lane == 31) wsum[wid] = x;
    __syncthreads();
    if (t == 0) {
        int run = 0;
        #pragma unroll
        for (int k = 0; k < 8; k++) { int v = wsum[k]; wsum[k] = run; run += v; }
        blockbase = atomicAdd(&g_base, run);
    }
    __syncthreads();
    if (i < N_ENT) g_off[i] = blockbase + wsum[wid] + (x - d);
}

// ================= K3: atomic-free edge scatter, 4 edges/thread ==========
__global__ void k_fill(const int* __restrict__ src, const int* __restrict__ dst,
                       const int* __restrict__ rid) {
    int t = blockIdx.x * blockDim.x + threadIdx.x;
    if (t >= N_EDGE / 4) return;
    int4 d4 = ((const int4*)dst)[t];
    int4 s4 = ((const int4*)src)[t];
    int4 i4 = ((const int4*)rid)[t];
    int4 r4 = ((const int4*)g_rank)[t];
    g_pk[g_off[d4.x] + r4.x] = (unsigned)s4.x * 512u + (unsigned)i4.x;
    g_pk[g_off[d4.y] + r4.y] = (unsigned)s4.y * 512u + (unsigned)i4.y;
    g_pk[g_off[d4.z] + r4.z] = (unsigned)s4.z * 512u + (unsigned)i4.z;
    g_pk[g_off[d4.w] + r4.w] = (unsigned)s4.w * 512u + (unsigned)i4.w;
}

// ================= K4: warp-per-node agg, butterfly + f32x2 math =========
__global__ void __launch_bounds__(256)
k_agg(const float* __restrict__ ent, const float* __restrict__ rel) {
    const unsigned F = 0xffffffffu;
    int w    = (blockIdx.x * blockDim.x + threadIdx.x) >> 5;
    int lane = threadIdx.x & 31;
    if (w >= N_ENT) return;

    ulonglong2 rv = ((const ulonglong2*)(ent + (size_t)w * H))[lane];
    ull v01 = rv.x, v23 = rv.y;
    int start = g_off[w];
    int end   = start + g_deg[w];

    ull a0_01 = 0, a0_23 = 0, a1_01 = 0, a1_23 = 0, a2_01 = 0, a2_23 = 0;
    float s0 = 0.f, s1 = 0.f, s2 = 0.f;

    unsigned nA = 0, nB = 0;
    if (start < end) {
        nA = g_pk[start];
        nB = (start + 1 < end) ? g_pk[start + 1] : nA;
    }
    for (int i = start; i < end; i += 2) {
        unsigned pA = nA, pB = nB;
        int hasB = (i + 1 < end);
        int j = i + 2;
        if (j < end) {
            nA = g_pk[j];
            nB = (j + 1 < end) ? g_pk[j + 1] : nA;
        }

        ulonglong2 ruA = ((const ulonglong2*)(ent + (size_t)(pA >> 9) * H))[lane];
        ulonglong2 rqA = ((const ulonglong2*)(rel + (size_t)(pA & 511u) * H))[lane];
        ulonglong2 ruB = ((const ulonglong2*)(ent + (size_t)(pB >> 9) * H))[lane];
        ulonglong2 rqB = ((const ulonglong2*)(rel + (size_t)(pB & 511u) * H))[lane];

        float dnA = dot4p(ruA.x, ruA.y, v01, v23);
        float deA = dot4p(rqA.x, rqA.y, v01, v23);
        float dnB = dot4p(ruB.x, ruB.y, v01, v23);
        float deB = dot4p(rqB.x, rqB.y, v01, v23);

        // folded butterfly: 9 SHFL + 9 ADD + 3 SEL for all 4 totals
        float rA  = dnA + __shfl_xor_sync(F, dnA, 16);
        float rAe = deA + __shfl_xor_sync(F, deA, 16);
        float rB  = dnB + __shfl_xor_sync(F, dnB, 16);
        float rBe = deB + __shfl_xor_sync(F, deB, 16);
        float x = (lane & 16) ? rB  : rA;
        float y = (lane & 16) ? rBe : rAe;
        float sx = x + __shfl_xor_sync(F, x, 8);
        float sy = y + __shfl_xor_sync(F, y, 8);
        float zz = (lane & 8) ? sy : sx;
        zz += __shfl_xor_sync(F, zz, 4);
        zz += __shfl_xor_sync(F, zz, 2);
        zz += __shfl_xor_sync(F, zz, 1);
        float ev = __expf(zz);
        float nAx = __shfl_sync(F, ev, 0);
        float eA  = __shfl_sync(F, ev, 8);
        float nBx = __shfl_sync(F, ev, 16);
        float eB  = __shfl_sync(F, ev, 24);

        float cA = eA * nAx;
        s0 += eA; s1 += nAx; s2 += cA;
        {
            ull e2 = dup2(eA), n2 = dup2(nAx), c2 = dup2(cA);
            fma2(a0_01, e2, rqA.x); fma2(a0_23, e2, rqA.y);
            fma2(a1_01, n2, ruA.x); fma2(a1_23, n2, ruA.y);
            ull uq01 = add2(ruA.x, rqA.x), uq23 = add2(ruA.y, rqA.y);
            fma2(a2_01, c2, uq01);  fma2(a2_23, c2, uq23);
        }
        if (hasB) {
            float cB = eB * nBx;
            s0 += eB; s1 += nBx; s2 += cB;
            ull e2 = dup2(eB), n2 = dup2(nBx), c2 = dup2(cB);
            fma2(a0_01, e2, rqB.x); fma2(a0_23, e2, rqB.y);
            fma2(a1_01, n2, ruB.x); fma2(a1_23, n2, ruB.y);
            ull uq01 = add2(ruB.x, rqB.x), uq23 = add2(ruB.y, rqB.y);
            fma2(a2_01, c2, uq01);  fma2(a2_23, c2, uq23);
        }
    }

    float i0 = (end > start) ? 1.f / s0 : 0.f;
    float i1 = (end > start) ? 1.f / s1 : 0.f;
    float i2 = (end > start) ? 1.f / s2 : 0.f;
    float2 A0 = unp2(mul2(a0_01, dup2(i0))), A0h = unp2(mul2(a0_23, dup2(i0)));
    float2 A1 = unp2(mul2(a1_01, dup2(i1))), A1h = unp2(mul2(a1_23, dup2(i1)));
    float2 A2 = unp2(mul2(a2_01, dup2(i2))), A2h = unp2(mul2(a2_23, dup2(i2)));
    size_t off = (size_t)w * H + lane * 4;
    *(__half2*)&g_a[0][off]     = __floats2half2_rn(A0.x, A0.y);
    *(__half2*)&g_a[0][off + 2] = __floats2half2_rn(A0h.x, A0h.y);
    *(__half2*)&g_a[1][off]     = __floats2half2_rn(A1.x, A1.y);
    *(__half2*)&g_a[1][off + 2] = __floats2half2_rn(A1h.x, A1h.y);
    *(__half2*)&g_a[2][off]     = __floats2half2_rn(A2.x, A2.y);
    *(__half2*)&g_a[2][off + 2] = __floats2half2_rn(A2h.x, A2h.y);
}

// ================= K5: fp16 HMMA GEMM, cross-layer register accumulator ===
#define PITCH    272
#define TILE_B   (128 * PITCH)          // 34816
#define SM_A0    0
#define SM_A1    TILE_B
#define SM_W     (2 * TILE_B)
#define SM_TOT   (3 * TILE_B)           // 104448

__device__ __forceinline__ void fill_tile_async(uint32_t smbase, const uint4* src, int tid) {
    #pragma unroll
    for (int i = 0; i < 8; i++) {
        int idx = i * 256 + tid;
        int row = idx >> 4, ch = idx & 15;
        CP16(smbase + (uint32_t)(row * PITCH + ch * 16), src + idx);
    }
}

__global__ void __launch_bounds__(256, 2)
k_gemm3(const float* __restrict__ ent, float* __restrict__ out) {
    extern __shared__ char sm[];
    uint32_t sb = smem_u32(sm);
    int tid  = threadIdx.x;
    int wid  = tid >> 5;
    int lane = tid & 31;
    int row0 = blockIdx.x * 128;

    // re-zero scratch for next graph replay (dead after k_agg)
    int z = blockIdx.x * 256 + tid;
    if (z < N_ENT) g_deg[z] = 0;
    if (z == N_ENT) g_base = 0;

    int q = lane >> 3, r = lane & 7;
    uint32_t a_off = (uint32_t)((wid * 16 + r + (q & 1) * 8) * PITCH + (q >> 1) * 16);
    uint32_t b_off = (uint32_t)(((q >> 1) * 8 + r) * PITCH + (q & 1) * 16);

    fill_tile_async(sb + SM_A0, (const uint4*)(g_a[0] + (size_t)row0 * H), tid);
    fill_tile_async(sb + SM_W,  (const uint4*)(g_wt[0]), tid);
    CP_COMMIT();
    CP_WAIT0();
    __syncthreads();

    float acc[16][4];
    #pragma unroll
    for (int nt = 0; nt < 16; nt++)
        #pragma unroll
        for (int j = 0; j < 4; j++) acc[nt][j] = 0.f;

    int cur = 0;
    for (int layer = 0; layer < 3; layer++) {
        if (layer < 2) {
            fill_tile_async(sb + (cur ? SM_A0 : SM_A1),
                            (const uint4*)(g_a[layer + 1] + (size_t)row0 * H), tid);
            CP_COMMIT();
        }

        uint32_t ab = sb + (cur ? SM_A1 : SM_A0) + a_off;
        uint32_t bb = sb + SM_W + b_off;

        #pragma unroll
        for (int nh = 0; nh < 2; nh++) {
            float c[8][4];
            #pragma unroll
            for (int nt = 0; nt < 8; nt++)
                #pragma unroll
                for (int j = 0; j < 4; j++) c[nt][j] = 0.f;

            #pragma unroll
            for (int ks = 0; ks < 8; ks++) {
                uint32_t aa0, aa1, aa2, aa3;
                LDSM4(aa0, aa1, aa2, aa3, ab + ks * 32);
                #pragma unroll
                for (int np = 0; np < 4; np++) {
                    uint32_t b0, b1, b2, b3;
                    LDSM4(b0, b1, b2, b3,
                          bb + (nh * 4 + np) * (16 * PITCH) + ks * 32);
                    MMA16816(c[np * 2],     aa0, aa1, aa2, aa3, b0, b1);
                    MMA16816(c[np * 2 + 1], aa0, aa1, aa2, aa3, b2, b3);
                }
            }
            #pragma unroll
            for (int nt = 0; nt < 8; nt++)
                #pragma unroll
                for (int j = 0; j < 4; j++)
                    acc[nh * 8 + nt][j] += fast_tanh(c[nt][j]);
        }

        __syncthreads();
        if (layer < 2) {
            fill_tile_async(sb + SM_W, (const uint4*)(g_wt[layer + 1]), tid);
            CP_COMMIT();
            CP_WAIT0();
            __syncthreads();
            cur ^= 1;
        }
    }

    // single write: out = ent + acc
    int m0 = row0 + wid * 16 + (lane >> 2);
    int nb = (lane & 3) * 2;
    #pragma unroll
    for (int nt = 0; nt < 16; nt++) {
        int n = nt * 8 + nb;
        if (m0 < N_ENT) {
            const float2* ep = (const float2*)(ent + (size_t)m0 * H + n);
            float2 v0 = *ep;
            v0.x += acc[nt][0];
            v0.y += acc[nt][1];
            *(float2*)(out + (size_t)m0 * H + n) = v0;
        }
        if (m0 + 8 < N_ENT) {
            const float2* ep = (const float2*)(ent + (size_t)(m0 + 8) * H + n);
            float2 v1 = *ep;
            v1.x += acc[nt][2];
            v1.y += acc[nt][3];
            *(float2*)(out + (size_t)(m0 + 8) * H + n) = v1;
        }
    }
}

// ================= launch =================
extern "C" void kernel_launch(void* const* d_in, const int* in_sizes, int n_in,
                              void* d_out, int out_size) {
    const float* ent    = (const float*)d_in[0];
    const float* rel    = (const float*)d_in[1];
    const float* w_edge = (const float*)d_in[2];
    const float* w_node = (const float*)d_in[3];
    const float* w_comp = (const float*)d_in[4];
    const int*   src    = (const int*)d_in[5];
    const int*   dst    = (const int*)d_in[6];
    const int*   rid    = (const int*)d_in[7];
    float*       out    = (float*)d_out;

    cudaFuncSetAttribute(k_gemm3, cudaFuncAttributeMaxDynamicSharedMemorySize, SM_TOT);

    // g_deg/g_base are zero at load and re-zeroed by k_gemm3 every call.
    k_hist <<<(N_EDGE / 4 + 255) / 256, 256>>>(dst);           // launch 1
    k_alloc<<<196, 256>>>(w_edge, w_node, w_comp);             // launch 2
    k_fill <<<(N_EDGE / 4 + 255) / 256, 256>>>(src, dst, rid); // launch 3
    k_agg  <<<N_ENT / 8, 256>>>(ent, rel);                     // launch 4 <- profiled
    k_gemm3<<<N_PAD / 128, 256, SM_TOT>>>(ent, out);           // launch 5
}

// round 17
// speedup vs baseline: 1.0158x; 1.0158x over previous
#include <cuda_runtime.h>
#include <cuda_fp16.h>
#include <math.h>
#include <stdint.h>

#define N_ENT  50000
#define N_PAD  50048           // 391 * 128
#define N_EDGE 500000
#define H      128

// ================= scratch (static __device__, zero-init at load) =========
// g_deg and g_base are re-zeroed by k_gemm3 at the end of every call.
__device__ int      g_deg[N_ENT];
__device__ int      g_off[N_ENT];
__device__ int      g_base;
__device__ __align__(16) int      g_rank[N_EDGE];  // edge rank within dst segment
__device__ unsigned g_pk[N_EDGE];                  // packed src*512 + rel_id
__device__ __align__(16) __half g_a[3][N_PAD * H]; // neigh fp16 (pad rows stay 0)
__device__ __align__(16) __half g_wt[3][H * H];    // W^T fp16 (h-major rows)

// ================= helpers =================
__device__ __forceinline__ float dot4(float4 a, float4 b) {
    return a.x * b.x + a.y * b.y + a.z * b.z + a.w * b.w;
}
__device__ __forceinline__ float fast_tanh(float x) {
    float e = __expf(2.f * x);
    return 1.f - __fdividef(2.f, e + 1.f);
}
__device__ __forceinline__ float ex2(float x) {
    float r; asm("ex2.approx.f32 %0, %1;" : "=f"(r) : "f"(x)); return r;
}
__device__ __forceinline__ uint32_t smem_u32(const void* p) {
    uint32_t a;
    asm("{ .reg .u64 t; cvta.to.shared.u64 t, %1; cvt.u32.u64 %0, t; }" : "=r"(a) : "l"(p));
    return a;
}
#define LDSM4(R0, R1, R2, R3, addr) \
    asm volatile("ldmatrix.sync.aligned.m8n8.x4.shared.b16 {%0,%1,%2,%3}, [%4];" \
        : "=r"(R0), "=r"(R1), "=r"(R2), "=r"(R3) : "r"(addr))
#define MMA16816(C, A0, A1, A2, A3, B0, B1) \
    asm volatile("mma.sync.aligned.m16n8k16.row.col.f32.f16.f16.f32 " \
        "{%0,%1,%2,%3}, {%4,%5,%6,%7}, {%8,%9}, {%0,%1,%2,%3};" \
        : "+f"((C)[0]), "+f"((C)[1]), "+f"((C)[2]), "+f"((C)[3]) \
        : "r"(A0), "r"(A1), "r"(A2), "r"(A3), "r"(B0), "r"(B1))
#define CP16(sm_addr, gptr) \
    asm volatile("cp.async.cg.shared.global [%0], [%1], 16;" :: "r"(sm_addr), "l"(gptr))
#define CP_COMMIT() asm volatile("cp.async.commit_group;")
#define CP_WAIT0()  asm volatile("cp.async.wait_group 0;")

// ================= K1: degree histogram, 4 edges/thread ==================
__global__ void k_hist(const int* __restrict__ dst) {
    int t = blockIdx.x * blockDim.x + threadIdx.x;
    if (t >= N_EDGE / 4) return;
    int4 d4 = ((const int4*)dst)[t];
    int4 r4;
    r4.x = atomicAdd(&g_deg[d4.x], 1);
    r4.y = atomicAdd(&g_deg[d4.y], 1);
    r4.z = atomicAdd(&g_deg[d4.z], 1);
    r4.w = atomicAdd(&g_deg[d4.w], 1);
    ((int4*)g_rank)[t] = r4;
}

// ================= K2: parallel CSR offsets + W^T fp16 prep ==============
__global__ void __launch_bounds__(256)
k_alloc(const float* __restrict__ we, const float* __restrict__ wn,
        const float* __restrict__ wc) {
    int t = threadIdx.x;
    int i = blockIdx.x * 256 + t;

    if (i < 3 * H * H) {
        int l = i >> 14, r = i & 16383;
        int k = r >> 7, h = r & 127;
        const float* W = (l == 0) ? we : (l == 1) ? wn : wc;
        g_wt[l][h * H + k] = __float2half(W[k * H + h]);
    }

    int d = (i < N_ENT) ? g_deg[i] : 0;
    int lane = t & 31, wid = t >> 5;
    int x = d;
    #pragma unroll
    for (int o = 1; o < 32; o <<= 1) {
        int y = __shfl_up_sync(0xffffffffu, x, o);
        if (lane >= o) x += y;
    }
    __shared__ int wsum[8];
    __shared__ int blockbase;
    if (lane == 31) wsum[wid] = x;
    __syncthreads();
    if (t == 0) {
        int run = 0;
        #pragma unroll
        for (int k = 0; k < 8; k++) { int v = wsum[k]; wsum[k] = run; run += v; }
        blockbase = atomicAdd(&g_base, run);
    }
    __syncthreads();
    if (i < N_ENT) g_off[i] = blockbase + wsum[wid] + (x - d);
}

// ================= K3: atomic-free edge scatter, 4 edges/thread ==========
__global__ void k_fill(const int* __restrict__ src, const int* __restrict__ dst,
                       const int* __restrict__ rid) {
    int t = blockIdx.x * blockDim.x + threadIdx.x;
    if (t >= N_EDGE / 4) return;
    int4 d4 = ((const int4*)dst)[t];
    int4 s4 = ((const int4*)src)[t];
    int4 i4 = ((const int4*)rid)[t];
    int4 r4 = ((const int4*)g_rank)[t];
    g_pk[g_off[d4.x] + r4.x] = (unsigned)s4.x * 512u + (unsigned)i4.x;
    g_pk[g_off[d4.y] + r4.y] = (unsigned)s4.y * 512u + (unsigned)i4.y;
    g_pk[g_off[d4.z] + r4.z] = (unsigned)s4.z * 512u + (unsigned)i4.z;
    g_pk[g_off[d4.w] + r4.w] = (unsigned)s4.w * 512u + (unsigned)i4.w;
}

// ================= K4: warp-per-node agg, butterfly + cheap addressing ===
// pk = src*512 + rel; an ent row is exactly 512 B, so the ent byte-offset
// is (pk & ~511) and the rel byte-offset is (pk & 511) << 9. Per-lane base
// pointers are hoisted, making each gather address LOP3+IADD.
// v is pre-scaled by log2(e) so the butterfly totals are log2-domain and
// exp becomes a single EX2.
__global__ void __launch_bounds__(256)
k_agg(const float* __restrict__ ent, const float* __restrict__ rel) {
    const unsigned F = 0xffffffffu;
    int w    = (blockIdx.x * blockDim.x + threadIdx.x) >> 5;
    int lane = threadIdx.x & 31;
    if (w >= N_ENT) return;

    const char* entb = (const char*)ent + (size_t)lane * 16;
    const char* relb = (const char*)rel + (size_t)lane * 16;

    float4 v = ((const float4*)(ent + (size_t)w * H))[lane];
    const float L2E = 1.4426950408889634f;
    v.x *= L2E; v.y *= L2E; v.z *= L2E; v.w *= L2E;

    int start = g_off[w];
    int end   = start + g_deg[w];

    float4 a0 = make_float4(0.f, 0.f, 0.f, 0.f), a1 = a0, a2 = a0;
    float s0 = 0.f, s1 = 0.f, s2 = 0.f;

    unsigned nA = 0, nB = 0;
    if (start < end) {
        nA = g_pk[start];
        nB = (start + 1 < end) ? g_pk[start + 1] : nA;
    }
    for (int i = start; i < end; i += 2) {
        unsigned pA = nA, pB = nB;
        int hasB = (i + 1 < end);
        int j = i + 2;
        if (j < end) {
            nA = g_pk[j];
            nB = (j + 1 < end) ? g_pk[j + 1] : nA;
        }

        float4 uA = *(const float4*)(entb + (pA & ~511u));
        float4 qA = *(const float4*)(relb + ((size_t)(pA & 511u) << 9));
        float4 uB = *(const float4*)(entb + (pB & ~511u));
        float4 qB = *(const float4*)(relb + ((size_t)(pB & 511u) << 9));

        float dnA = dot4(uA, v), deA = dot4(qA, v);
        float dnB = dot4(uB, v), deB = dot4(qB, v);

        // folded butterfly: 9 SHFL + 9 ADD + 3 SEL for all 4 totals
        float rA  = dnA + __shfl_xor_sync(F, dnA, 16);
        float rAe = deA + __shfl_xor_sync(F, deA, 16);
        float rB  = dnB + __shfl_xor_sync(F, dnB, 16);
        float rBe = deB + __shfl_xor_sync(F, deB, 16);
        float x = (lane & 16) ? rB  : rA;
        float y = (lane & 16) ? rBe : rAe;
        float sx = x + __shfl_xor_sync(F, x, 8);
        float sy = y + __shfl_xor_sync(F, y, 8);
        float zz = (lane & 8) ? sy : sx;
        zz += __shfl_xor_sync(F, zz, 4);
        zz += __shfl_xor_sync(F, zz, 2);
        zz += __shfl_xor_sync(F, zz, 1);
        float ev = ex2(zz);                          // log2-domain: single EX2
        float nAx = __shfl_sync(F, ev, 0);
        float eA  = __shfl_sync(F, ev, 8);
        float nBx = __shfl_sync(F, ev, 16);
        float eB  = __shfl_sync(F, ev, 24);

        float cA = eA * nAx;
        s0 += eA; s1 += nAx; s2 += cA;
        a0.x += eA * qA.x; a0.y += eA * qA.y; a0.z += eA * qA.z; a0.w += eA * qA.w;
        a1.x += nAx * uA.x; a1.y += nAx * uA.y; a1.z += nAx * uA.z; a1.w += nAx * uA.w;
        a2.x += cA * (uA.x + qA.x); a2.y += cA * (uA.y + qA.y);
        a2.z += cA * (uA.z + qA.z); a2.w += cA * (uA.w + qA.w);
        if (hasB) {
            float cB = eB * nBx;
            s0 += eB; s1 += nBx; s2 += cB;
            a0.x += eB * qB.x; a0.y += eB * qB.y; a0.z += eB * qB.z; a0.w += eB * qB.w;
            a1.x += nBx * uB.x; a1.y += nBx * uB.y; a1.z += nBx * uB.z; a1.w += nBx * uB.w;
            a2.x += cB * (uB.x + qB.x); a2.y += cB * (uB.y + qB.y);
            a2.z += cB * (uB.z + qB.z); a2.w += cB * (uB.w + qB.w);
        }
    }

    float i0 = (end > start) ? 1.f / s0 : 0.f;
    float i1 = (end > start) ? 1.f / s1 : 0.f;
    float i2 = (end > start) ? 1.f / s2 : 0.f;
    size_t off = (size_t)w * H + lane * 4;
    *(__half2*)&g_a[0][off]     = __floats2half2_rn(a0.x * i0, a0.y * i0);
    *(__half2*)&g_a[0][off + 2] = __floats2half2_rn(a0.z * i0, a0.w * i0);
    *(__half2*)&g_a[1][off]     = __floats2half2_rn(a1.x * i1, a1.y * i1);
    *(__half2*)&g_a[1][off + 2] = __floats2half2_rn(a1.z * i1, a1.w * i1);
    *(__half2*)&g_a[2][off]     = __floats2half2_rn(a2.x * i2, a2.y * i2);
    *(__half2*)&g_a[2][off + 2] = __floats2half2_rn(a2.z * i2, a2.w * i2);
}

// ================= K5: fp16 HMMA GEMM, cross-layer register accumulator ===
#define PITCH    272
#define TILE_B   (128 * PITCH)          // 34816
#define SM_A0    0
#define SM_A1    TILE_B
#define SM_W     (2 * TILE_B)
#define SM_TOT   (3 * TILE_B)           // 104448

__device__ __forceinline__ void fill_tile_async(uint32_t smbase, const uint4* src, int tid) {
    #pragma unroll
    for (int i = 0; i < 8; i++) {
        int idx = i * 256 + tid;
        int row = idx >> 4, ch = idx & 15;
        CP16(smbase + (uint32_t)(row * PITCH + ch * 16), src + idx);
    }
}

__global__ void __launch_bounds__(256, 2)
k_gemm3(const float* __restrict__ ent, float* __restrict__ out) {
    extern __shared__ char sm[];
    uint32_t sb = smem_u32(sm);
    int tid  = threadIdx.x;
    int wid  = tid >> 5;
    int lane = tid & 31;
    int row0 = blockIdx.x * 128;

    // re-zero scratch for next graph replay (dead after k_agg)
    int z = blockIdx.x * 256 + tid;
    if (z < N_ENT) g_deg[z] = 0;
    if (z == N_ENT) g_base = 0;

    int q = lane >> 3, r = lane & 7;
    uint32_t a_off = (uint32_t)((wid * 16 + r + (q & 1) * 8) * PITCH + (q >> 1) * 16);
    uint32_t b_off = (uint32_t)(((q >> 1) * 8 + r) * PITCH + (q & 1) * 16);

    fill_tile_async(sb + SM_A0, (const uint4*)(g_a[0] + (size_t)row0 * H), tid);
    fill_tile_async(sb + SM_W,  (const uint4*)(g_wt[0]), tid);
    CP_COMMIT();
    CP_WAIT0();
    __syncthreads();

    float acc[16][4];
    #pragma unroll
    for (int nt = 0; nt < 16; nt++)
        #pragma unroll
        for (int j = 0; j < 4; j++) acc[nt][j] = 0.f;

    int cur = 0;
    for (int layer = 0; layer < 3; layer++) {
        if (layer < 2) {
            fill_tile_async(sb + (cur ? SM_A0 : SM_A1),
                            (const uint4*)(g_a[layer + 1] + (size_t)row0 * H), tid);
            CP_COMMIT();
        }

        uint32_t ab = sb + (cur ? SM_A1 : SM_A0) + a_off;
        uint32_t bb = sb + SM_W + b_off;

        #pragma unroll
        for (int nh = 0; nh < 2; nh++) {
            float c[8][4];
            #pragma unroll
            for (int nt = 0; nt < 8; nt++)
                #pragma unroll
                for (int j = 0; j < 4; j++) c[nt][j] = 0.f;

            #pragma unroll
            for (int ks = 0; ks < 8; ks++) {
                uint32_t aa0, aa1, aa2, aa3;
                LDSM4(aa0, aa1, aa2, aa3, ab + ks * 32);
                #pragma unroll
                for (int np = 0; np < 4; np++) {
                    uint32_t b0, b1, b2, b3;
                    LDSM4(b0, b1, b2, b3,
                          bb + (nh * 4 + np) * (16 * PITCH) + ks * 32);
                    MMA16816(c[np * 2],     aa0, aa1, aa2, aa3, b0, b1);
                    MMA16816(c[np * 2 + 1], aa0, aa1, aa2, aa3, b2, b3);
                }
            }
            #pragma unroll
            for (int nt = 0; nt < 8; nt++)
                #pragma unroll
                for (int j = 0; j < 4; j++)
                    acc[nh * 8 + nt][j] += fast_tanh(c[nt][j]);
        }

        __syncthreads();
        if (layer < 2) {
            fill_tile_async(sb + SM_W, (const uint4*)(g_wt[layer + 1]), tid);
            CP_COMMIT();
            CP_WAIT0();
            __syncthreads();
            cur ^= 1;
        }
    }

    // single write: out = ent + acc
    int m0 = row0 + wid * 16 + (lane >> 2);
    int nb = (lane & 3) * 2;
    #pragma unroll
    for (int nt = 0; nt < 16; nt++) {
        int n = nt * 8 + nb;
        if (m0 < N_ENT) {
            const float2* ep = (const float2*)(ent + (size_t)m0 * H + n);
            float2 v0 = *ep;
            v0.x += acc[nt][0];
            v0.y += acc[nt][1];
            *(float2*)(out + (size_t)m0 * H + n) = v0;
        }
        if (m0 + 8 < N_ENT) {
            const float2* ep = (const float2*)(ent + (size_t)(m0 + 8) * H + n);
            float2 v1 = *ep;
            v1.x += acc[nt][2];
            v1.y += acc[nt][3];
            *(float2*)(out + (size_t)(m0 + 8) * H + n) = v1;
        }
    }
}

// ================= launch =================
extern "C" void kernel_launch(void* const* d_in, const int* in_sizes, int n_in,
                              void* d_out, int out_size) {
    const float* ent    = (const float*)d_in[0];
    const float* rel    = (const float*)d_in[1];
    const float* w_edge = (const float*)d_in[2];
    const float* w_node = (const float*)d_in[3];
    const float* w_comp = (const float*)d_in[4];
    const int*   src    = (const int*)d_in[5];
    const int*   dst    = (const int*)d_in[6];
    const int*   rid    = (const int*)d_in[7];
    float*       out    = (float*)d_out;

    cudaFuncSetAttribute(k_gemm3, cudaFuncAttributeMaxDynamicSharedMemorySize, SM_TOT);

    // g_deg/g_base are zero at load and re-zeroed by k_gemm3 every call.
    k_hist <<<(N_EDGE / 4 + 255) / 256, 256>>>(dst);           // launch 1
    k_alloc<<<196, 256>>>(w_edge, w_node, w_comp);             // launch 2
    k_fill <<<(N_EDGE / 4 + 255) / 256, 256>>>(src, dst, rid); // launch 3
    k_agg  <<<N_ENT / 8, 256>>>(ent, rel);                     // launch 4 <- profiled
    k_gemm3<<<N_PAD / 128, 256, SM_TOT>>>(ent, out);           // launch 5
}